// round 5
// baseline (speedup 1.0000x reference)
#include <cuda_runtime.h>
#include <cuda_bf16.h>

#define T_STEPS 1000
#define NB 64
#define NH 512
#define NIN 256

// Constants derived exactly as the Python reference does (double math, then fp32 cast)
#define C_MEM  ((float)(0.001 * (1.0 / 1e-2)))     // DT * TAU_MEM_INV   = 0.1
#define C_SYN  ((float)(0.001 * (1.0 / 5e-3)))     // DT * TAU_SYN_INV   = 0.2
#define C_AD   ((float)(0.001 * (1.0 / 800.0)))    // DT * TAU_ADAPT_INV
#define C_JP   ((float)((1.0 / 800.0) * 1.8))      // TAU_ADAPT_INV * BETA

// Pipeline: 4 rows per commit group, 6 groups in flight, ring of 8 block-slots (32 rows)
#define NPF 6
#define RING_ROWS 32
#define RING_BYTES (RING_ROWS * NH * 4)

__device__ __align__(16) float g_xin[(size_t)T_STEPS * NB * NH];
__device__ __align__(16) float g_wrecT[(NH + 1) * NH];

#define CP_ASYNC16(dst_u32, src_ptr) \
    asm volatile("cp.async.cg.shared.global [%0], [%1], 16;" :: "r"(dst_u32), "l"(src_ptr) : "memory")
#define CP_COMMIT() asm volatile("cp.async.commit_group;" ::: "memory")
#define CP_WAIT(n)  asm volatile("cp.async.wait_group %0;" :: "n"(n) : "memory")

// ---------------------------------------------------------------------------
// Transpose w_rec (NH x NH, row-major [n][m]) -> g_wrecT[m][n]
// ---------------------------------------------------------------------------
__global__ void transpose_wrec(const float* __restrict__ W) {
    __shared__ float tile[32][33];
    int mb = blockIdx.x * 32;
    int nb = blockIdx.y * 32;
    #pragma unroll
    for (int j = threadIdx.y; j < 32; j += 8)
        tile[j][threadIdx.x] = W[(size_t)(nb + j) * NH + mb + threadIdx.x];
    __syncthreads();
    #pragma unroll
    for (int j = threadIdx.y; j < 32; j += 8)
        g_wrecT[(size_t)(mb + j) * NH + nb + threadIdx.x] = tile[threadIdx.x][j];
}

__global__ void zero_pad_row() {
    g_wrecT[(size_t)NH * NH + threadIdx.x] = 0.0f;
}

// ---------------------------------------------------------------------------
// Input GEMM: Y[r,n] = sum_k X[r,k] * Win[n,k]
// Per-element accumulation strictly sequential over k with fused FMA.
// ---------------------------------------------------------------------------
__global__ void __launch_bounds__(256) gemm_in(const float* __restrict__ X,
                                               const float* __restrict__ Win) {
    __shared__ float As[32][68];
    __shared__ float Bs[32][68];

    const int t  = threadIdx.x;
    const int r0 = blockIdx.x * 64;
    const int n0 = blockIdx.y * 64;

    const int lm = t >> 3;
    const int lk = (t & 7) * 4;
    const int tx = t & 15;
    const int ty = t >> 4;

    float acc[4][4];
    #pragma unroll
    for (int i = 0; i < 4; i++)
        #pragma unroll
        for (int j = 0; j < 4; j++) acc[i][j] = 0.0f;

    for (int kt = 0; kt < NIN; kt += 32) {
        #pragma unroll
        for (int h = 0; h < 2; h++) {
            int m = lm + 32 * h;
            float4 a = *(const float4*)(X + (size_t)(r0 + m) * NIN + kt + lk);
            As[lk + 0][m] = a.x; As[lk + 1][m] = a.y;
            As[lk + 2][m] = a.z; As[lk + 3][m] = a.w;
            float4 b = *(const float4*)(Win + (size_t)(n0 + m) * NIN + kt + lk);
            Bs[lk + 0][m] = b.x; Bs[lk + 1][m] = b.y;
            Bs[lk + 2][m] = b.z; Bs[lk + 3][m] = b.w;
        }
        __syncthreads();

        #pragma unroll
        for (int kk = 0; kk < 32; kk++) {
            float4 av = *(const float4*)(&As[kk][4 * ty]);
            float4 bv = *(const float4*)(&Bs[kk][4 * tx]);
            float am[4] = {av.x, av.y, av.z, av.w};
            float bn[4] = {bv.x, bv.y, bv.z, bv.w};
            #pragma unroll
            for (int i = 0; i < 4; i++)
                #pragma unroll
                for (int j = 0; j < 4; j++)
                    acc[i][j] = __fmaf_rn(am[i], bn[j], acc[i][j]);
        }
        __syncthreads();
    }

    #pragma unroll
    for (int i = 0; i < 4; i++) {
        float4 o = make_float4(acc[i][0], acc[i][1], acc[i][2], acc[i][3]);
        *(float4*)(g_xin + (size_t)(r0 + 4 * ty + i) * NH + n0 + 4 * tx) = o;
    }
}

// ---------------------------------------------------------------------------
// Persistent recurrent kernel: 1 CTA per batch, 128 threads, 4 neurons/thread.
// Gather pipelined via cp.async into an SMEM ring: each thread copies ONLY its
// own 16B column slice of each spiking row (producer == consumer, so
// cp.async.wait_group alone orders it — no barriers inside the gather).
// Accumulation stays strictly sequential in ascending spike index (bit-exact).
// ---------------------------------------------------------------------------
__global__ void __launch_bounds__(128, 1) lsnn_recurrent(
    const float* __restrict__ z0, const float* __restrict__ v0,
    const float* __restrict__ i0, const float* __restrict__ b0,
    float* __restrict__ out, int write_tail) {

    extern __shared__ __align__(16) float s_ring[];   // RING_ROWS * NH floats

    const int b    = blockIdx.x;
    const int tid  = threadIdx.x;
    const int lane = tid & 31;
    const int wrp  = tid >> 5;
    const int n4   = tid * 4;

    __shared__ __align__(16) int s_list[NH + 4];
    __shared__ unsigned s_masks[16];

    unsigned ring_u32;
    {
        unsigned long long gp = __cvta_generic_to_shared(s_ring);
        ring_u32 = (unsigned)gp;
    }

    const size_t sb = (size_t)b * NH + n4;
    float4 v  = *(const float4*)(v0 + sb);
    float4 cu = *(const float4*)(i0 + sb);
    float4 ba = *(const float4*)(b0 + sb);
    float4 z  = *(const float4*)(z0 + sb);

    // Build spike list (ascending neuron index) from ballot masks. Returns nblk.
    auto build = [&](const float4& zz) -> int {
        unsigned m0 = __ballot_sync(0xffffffffu, zz.x != 0.0f);
        unsigned m1 = __ballot_sync(0xffffffffu, zz.y != 0.0f);
        unsigned m2 = __ballot_sync(0xffffffffu, zz.z != 0.0f);
        unsigned m3 = __ballot_sync(0xffffffffu, zz.w != 0.0f);
        if (lane == 0) {
            s_masks[wrp * 4 + 0] = m0;
            s_masks[wrp * 4 + 1] = m1;
            s_masks[wrp * 4 + 2] = m2;
            s_masks[wrp * 4 + 3] = m3;
        }
        __syncthreads();
        int cnt = 0, mybase = 0;
        #pragma unroll
        for (int w = 0; w < 4; w++) {
            int s = __popc(s_masks[w * 4 + 0]) + __popc(s_masks[w * 4 + 1])
                  + __popc(s_masks[w * 4 + 2]) + __popc(s_masks[w * 4 + 3]);
            if (w < wrp) mybase += s;
            cnt += s;
        }
        unsigned lt = (1u << lane) - 1u;
        int off = __popc(m0 & lt) + __popc(m1 & lt) + __popc(m2 & lt) + __popc(m3 & lt);
        int pos = mybase + off;
        if (m0 & (1u << lane)) s_list[pos++] = n4 + 0;
        if (m1 & (1u << lane)) s_list[pos++] = n4 + 1;
        if (m2 & (1u << lane)) s_list[pos++] = n4 + 2;
        if (m3 & (1u << lane)) s_list[pos++] = n4 + 3;
        int cntp = (cnt + 3) & ~3;
        if (tid == 0)
            for (int p = cnt; p < cntp; p++) s_list[p] = NH;   // zero row, adds +0.0 exactly
        __syncthreads();
        return cntp >> 2;
    };

    // Issue one 4-row block g: copy own 16B slice of rows list[4g..4g+3]
    auto issue_block = [&](int g) {
        int4 id = *(const int4*)(s_list + 4 * g);
        unsigned dst = ring_u32 + ((unsigned)(((g & 7) * 4) * NH + n4) << 2);
        CP_ASYNC16(dst,              g_wrecT + (size_t)id.x * NH + n4);
        CP_ASYNC16(dst + NH * 4,     g_wrecT + (size_t)id.y * NH + n4);
        CP_ASYNC16(dst + 2 * NH * 4, g_wrecT + (size_t)id.z * NH + n4);
        CP_ASYNC16(dst + 3 * NH * 4, g_wrecT + (size_t)id.w * NH + n4);
    };

    int nblk = build(z);

    const float* xin_p = g_xin + sb;
    float*       out_p = out + sb;

    for (int t = 0; t < T_STEPS; t++) {
        float4 xin = __ldcs((const float4*)xin_p);
        xin_p += NB * NH;

        // ---- pipelined gather ----
        #pragma unroll 1
        for (int g = 0; g < NPF; g++) {
            if (g < nblk) issue_block(g);
            CP_COMMIT();
        }
        float rx = 0.0f, ry = 0.0f, rz = 0.0f, rw = 0.0f;
        #pragma unroll 1
        for (int blk = 0; blk < nblk; blk++) {
            CP_WAIT(NPF - 1);
            const float* rp = s_ring + ((blk & 7) * 4) * NH + n4;
            float4 w0 = *(const float4*)(rp);
            float4 w1 = *(const float4*)(rp + NH);
            float4 w2 = *(const float4*)(rp + 2 * NH);
            float4 w3 = *(const float4*)(rp + 3 * NH);
            int nb2 = blk + NPF;
            if (nb2 < nblk) issue_block(nb2);
            CP_COMMIT();
            // strictly ascending spike order per component
            rx = __fadd_rn(rx, w0.x); ry = __fadd_rn(ry, w0.y);
            rz = __fadd_rn(rz, w0.z); rw = __fadd_rn(rw, w0.w);
            rx = __fadd_rn(rx, w1.x); ry = __fadd_rn(ry, w1.y);
            rz = __fadd_rn(rz, w1.z); rw = __fadd_rn(rw, w1.w);
            rx = __fadd_rn(rx, w2.x); ry = __fadd_rn(ry, w2.y);
            rz = __fadd_rn(rz, w2.z); rw = __fadd_rn(rw, w2.w);
            rx = __fadd_rn(rx, w3.x); ry = __fadd_rn(ry, w3.y);
            rz = __fadd_rn(rz, w3.z); rw = __fadd_rn(rw, w3.w);
        }

        // ---- elementwise LSNN update (FMA-contracted, matches reference backend) ----
        float vd0 = __fmaf_rn(C_MEM, __fadd_rn(__fsub_rn(0.0f, v.x), cu.x), v.x);
        float vd1 = __fmaf_rn(C_MEM, __fadd_rn(__fsub_rn(0.0f, v.y), cu.y), v.y);
        float vd2 = __fmaf_rn(C_MEM, __fadd_rn(__fsub_rn(0.0f, v.z), cu.z), v.z);
        float vd3 = __fmaf_rn(C_MEM, __fadd_rn(__fsub_rn(0.0f, v.w), cu.w), v.w);
        float bd0 = __fmaf_rn(C_AD, __fsub_rn(1.0f, ba.x), ba.x);
        float bd1 = __fmaf_rn(C_AD, __fsub_rn(1.0f, ba.y), ba.y);
        float bd2 = __fmaf_rn(C_AD, __fsub_rn(1.0f, ba.z), ba.z);
        float bd3 = __fmaf_rn(C_AD, __fsub_rn(1.0f, ba.w), ba.w);
        float zz0 = (__fsub_rn(vd0, bd0) > 0.0f) ? 1.0f : 0.0f;
        float zz1 = (__fsub_rn(vd1, bd1) > 0.0f) ? 1.0f : 0.0f;
        float zz2 = (__fsub_rn(vd2, bd2) > 0.0f) ? 1.0f : 0.0f;
        float zz3 = (__fsub_rn(vd3, bd3) > 0.0f) ? 1.0f : 0.0f;
        v.x = (zz0 != 0.0f) ? 0.0f : __fadd_rn(vd0, 0.0f);
        v.y = (zz1 != 0.0f) ? 0.0f : __fadd_rn(vd1, 0.0f);
        v.z = (zz2 != 0.0f) ? 0.0f : __fadd_rn(vd2, 0.0f);
        v.w = (zz3 != 0.0f) ? 0.0f : __fadd_rn(vd3, 0.0f);
        ba.x = __fadd_rn(bd0, (zz0 != 0.0f) ? C_JP : 0.0f);
        ba.y = __fadd_rn(bd1, (zz1 != 0.0f) ? C_JP : 0.0f);
        ba.z = __fadd_rn(bd2, (zz2 != 0.0f) ? C_JP : 0.0f);
        ba.w = __fadd_rn(bd3, (zz3 != 0.0f) ? C_JP : 0.0f);
        float id0 = __fmaf_rn(-C_SYN, cu.x, cu.x);
        float id1 = __fmaf_rn(-C_SYN, cu.y, cu.y);
        float id2 = __fmaf_rn(-C_SYN, cu.z, cu.z);
        float id3 = __fmaf_rn(-C_SYN, cu.w, cu.w);
        cu.x = __fadd_rn(__fadd_rn(id0, xin.x), rx);
        cu.y = __fadd_rn(__fadd_rn(id1, xin.y), ry);
        cu.z = __fadd_rn(__fadd_rn(id2, xin.z), rz);
        cu.w = __fadd_rn(__fadd_rn(id3, xin.w), rw);
        z.x = zz0; z.y = zz1; z.z = zz2; z.w = zz3;

        __stcs((float4*)out_p, z);
        out_p += NB * NH;

        nblk = build(z);
    }

    if (write_tail) {
        size_t base = (size_t)T_STEPS * NB * NH;
        *(float4*)(out + base + 0 * (size_t)NB * NH + sb) = z;
        *(float4*)(out + base + 1 * (size_t)NB * NH + sb) = v;
        *(float4*)(out + base + 2 * (size_t)NB * NH + sb) = cu;
        *(float4*)(out + base + 3 * (size_t)NB * NH + sb) = ba;
    }
}

// ---------------------------------------------------------------------------
extern "C" void kernel_launch(void* const* d_in, const int* in_sizes, int n_in,
                              void* d_out, int out_size) {
    const float* x     = (const float*)d_in[0];
    const float* z0    = (const float*)d_in[1];
    const float* v0    = (const float*)d_in[2];
    const float* i0    = (const float*)d_in[3];
    const float* b0    = (const float*)d_in[4];
    const float* w_in  = (const float*)d_in[5];
    const float* w_rec = (const float*)d_in[6];
    float* out = (float*)d_out;

    cudaFuncSetAttribute(lsnn_recurrent,
                         cudaFuncAttributeMaxDynamicSharedMemorySize, RING_BYTES);

    transpose_wrec<<<dim3(16, 16), dim3(32, 8)>>>(w_rec);
    zero_pad_row<<<1, NH>>>();
    gemm_in<<<dim3((T_STEPS * NB) / 64, NH / 64), 256>>>(x, w_in);

    long long need = (long long)T_STEPS * NB * NH + 4LL * NB * NH;
    int write_tail = ((long long)out_size >= need) ? 1 : 0;
    lsnn_recurrent<<<NB, 128, RING_BYTES>>>(z0, v0, i0, b0, out, write_tail);
}

// round 6
// speedup vs baseline: 2.8164x; 2.8164x over previous
#include <cuda_runtime.h>
#include <cuda_bf16.h>

#define T_STEPS 1000
#define NB 64
#define NH 512
#define NIN 256

// Constants derived exactly as the Python reference does (double math, then fp32 cast)
#define C_MEM  ((float)(0.001 * (1.0 / 1e-2)))     // DT * TAU_MEM_INV   = 0.1
#define C_SYN  ((float)(0.001 * (1.0 / 5e-3)))     // DT * TAU_SYN_INV   = 0.2
#define C_AD   ((float)(0.001 * (1.0 / 800.0)))    // DT * TAU_ADAPT_INV
#define C_JP   ((float)((1.0 / 800.0) * 1.8))      // TAU_ADAPT_INV * BETA

__device__ __align__(16) float g_xin[(size_t)T_STEPS * NB * NH];
__device__ __align__(16) float g_wrecT[(NH + 1) * NH];

// ---------------------------------------------------------------------------
// Transpose w_rec (NH x NH, row-major [n][m]) -> g_wrecT[m][n]
// ---------------------------------------------------------------------------
__global__ void transpose_wrec(const float* __restrict__ W) {
    __shared__ float tile[32][33];
    int mb = blockIdx.x * 32;
    int nb = blockIdx.y * 32;
    #pragma unroll
    for (int j = threadIdx.y; j < 32; j += 8)
        tile[j][threadIdx.x] = W[(size_t)(nb + j) * NH + mb + threadIdx.x];
    __syncthreads();
    #pragma unroll
    for (int j = threadIdx.y; j < 32; j += 8)
        g_wrecT[(size_t)(mb + j) * NH + nb + threadIdx.x] = tile[threadIdx.x][j];
}

__global__ void zero_pad_row() {
    g_wrecT[(size_t)NH * NH + threadIdx.x] = 0.0f;
}

// ---------------------------------------------------------------------------
// Input GEMM: Y[r,n] = sum_k X[r,k] * Win[n,k]
// Per-element accumulation strictly sequential over k with fused FMA.
// ---------------------------------------------------------------------------
__global__ void __launch_bounds__(256) gemm_in(const float* __restrict__ X,
                                               const float* __restrict__ Win) {
    __shared__ float As[32][68];
    __shared__ float Bs[32][68];

    const int t  = threadIdx.x;
    const int r0 = blockIdx.x * 64;
    const int n0 = blockIdx.y * 64;

    const int lm = t >> 3;
    const int lk = (t & 7) * 4;
    const int tx = t & 15;
    const int ty = t >> 4;

    float acc[4][4];
    #pragma unroll
    for (int i = 0; i < 4; i++)
        #pragma unroll
        for (int j = 0; j < 4; j++) acc[i][j] = 0.0f;

    for (int kt = 0; kt < NIN; kt += 32) {
        #pragma unroll
        for (int h = 0; h < 2; h++) {
            int m = lm + 32 * h;
            float4 a = *(const float4*)(X + (size_t)(r0 + m) * NIN + kt + lk);
            As[lk + 0][m] = a.x; As[lk + 1][m] = a.y;
            As[lk + 2][m] = a.z; As[lk + 3][m] = a.w;
            float4 b = *(const float4*)(Win + (size_t)(n0 + m) * NIN + kt + lk);
            Bs[lk + 0][m] = b.x; Bs[lk + 1][m] = b.y;
            Bs[lk + 2][m] = b.z; Bs[lk + 3][m] = b.w;
        }
        __syncthreads();

        #pragma unroll
        for (int kk = 0; kk < 32; kk++) {
            float4 av = *(const float4*)(&As[kk][4 * ty]);
            float4 bv = *(const float4*)(&Bs[kk][4 * tx]);
            float am[4] = {av.x, av.y, av.z, av.w};
            float bn[4] = {bv.x, bv.y, bv.z, bv.w};
            #pragma unroll
            for (int i = 0; i < 4; i++)
                #pragma unroll
                for (int j = 0; j < 4; j++)
                    acc[i][j] = __fmaf_rn(am[i], bn[j], acc[i][j]);
        }
        __syncthreads();
    }

    #pragma unroll
    for (int i = 0; i < 4; i++) {
        float4 o = make_float4(acc[i][0], acc[i][1], acc[i][2], acc[i][3]);
        *(float4*)(g_xin + (size_t)(r0 + 4 * ty + i) * NH + n0 + 4 * tx) = o;
    }
}

// ---------------------------------------------------------------------------
// Persistent recurrent kernel: 1 CTA per batch, 256 threads, 2 neurons/thread.
// Gather: direct LDG.64 -> registers, modulo-scheduled triple buffer of
// 8-row batches (24 rows in flight/warp) to cover L2 latency. Accumulation
// remains strictly sequential in ascending spike index (bit-exact).
// ---------------------------------------------------------------------------
__global__ void __launch_bounds__(256, 1) lsnn_recurrent(
    const float* __restrict__ z0, const float* __restrict__ v0,
    const float* __restrict__ i0, const float* __restrict__ b0,
    float* __restrict__ out, int write_tail) {

    const int b    = blockIdx.x;
    const int tid  = threadIdx.x;
    const int lane = tid & 31;
    const int wrp  = tid >> 5;
    const int n2   = tid * 2;

    __shared__ __align__(16) int s_list[NH + 24];
    __shared__ unsigned s_masks[16];

    const size_t sb = (size_t)b * NH + n2;
    float2 v  = *(const float2*)(v0 + sb);
    float2 cu = *(const float2*)(i0 + sb);
    float2 ba = *(const float2*)(b0 + sb);
    float2 z  = *(const float2*)(z0 + sb);

    // Build spike list (ascending neuron index). Pads to a multiple of 24
    // (minimum 24) with the zero row NH. Returns padded count.
    auto build = [&](const float2& zz) -> int {
        unsigned m0 = __ballot_sync(0xffffffffu, zz.x != 0.0f);
        unsigned m1 = __ballot_sync(0xffffffffu, zz.y != 0.0f);
        if (lane == 0) {
            s_masks[2 * wrp + 0] = m0;
            s_masks[2 * wrp + 1] = m1;
        }
        __syncthreads();
        int cnt = 0, mybase = 0;
        #pragma unroll
        for (int w = 0; w < 8; w++) {
            int s = __popc(s_masks[2 * w]) + __popc(s_masks[2 * w + 1]);
            if (w < wrp) mybase += s;
            cnt += s;
        }
        unsigned lt = (1u << lane) - 1u;
        int pos = mybase + __popc(m0 & lt) + __popc(m1 & lt);
        if (m0 & (1u << lane)) s_list[pos++] = n2;
        if (m1 & (1u << lane)) s_list[pos]   = n2 + 1;
        int cntp = ((cnt + 23) / 24) * 24;
        if (cntp == 0) cntp = 24;
        if (tid < cntp - cnt) s_list[cnt + tid] = NH;   // zero row: adds +0.0 exactly
        __syncthreads();
        return cntp;
    };

    int cntp = build(z);

    const float* xin_p = g_xin + sb;
    float*       out_p = out + sb;

    for (int t = 0; t < T_STEPS; t++) {
        float2 xin = __ldcs((const float2*)xin_p);
        xin_p += NB * NH;

        // ---- gather with register triple-buffer (batches of 8 rows) ----
        float2 RA[8], RB[8], RC[8];

        #define LOADB(R, base_k)                                            \
            do {                                                            \
                int4 _a = *(const int4*)(s_list + (base_k));                \
                int4 _b = *(const int4*)(s_list + (base_k) + 4);            \
                (R)[0] = *(const float2*)(g_wrecT + (size_t)_a.x * NH + n2);\
                (R)[1] = *(const float2*)(g_wrecT + (size_t)_a.y * NH + n2);\
                (R)[2] = *(const float2*)(g_wrecT + (size_t)_a.z * NH + n2);\
                (R)[3] = *(const float2*)(g_wrecT + (size_t)_a.w * NH + n2);\
                (R)[4] = *(const float2*)(g_wrecT + (size_t)_b.x * NH + n2);\
                (R)[5] = *(const float2*)(g_wrecT + (size_t)_b.y * NH + n2);\
                (R)[6] = *(const float2*)(g_wrecT + (size_t)_b.z * NH + n2);\
                (R)[7] = *(const float2*)(g_wrecT + (size_t)_b.w * NH + n2);\
            } while (0)

        #define CONSUME(R)                                                  \
            do {                                                            \
                recx = __fadd_rn(recx, (R)[0].x); recy = __fadd_rn(recy, (R)[0].y); \
                recx = __fadd_rn(recx, (R)[1].x); recy = __fadd_rn(recy, (R)[1].y); \
                recx = __fadd_rn(recx, (R)[2].x); recy = __fadd_rn(recy, (R)[2].y); \
                recx = __fadd_rn(recx, (R)[3].x); recy = __fadd_rn(recy, (R)[3].y); \
                recx = __fadd_rn(recx, (R)[4].x); recy = __fadd_rn(recy, (R)[4].y); \
                recx = __fadd_rn(recx, (R)[5].x); recy = __fadd_rn(recy, (R)[5].y); \
                recx = __fadd_rn(recx, (R)[6].x); recy = __fadd_rn(recy, (R)[6].y); \
                recx = __fadd_rn(recx, (R)[7].x); recy = __fadd_rn(recy, (R)[7].y); \
            } while (0)

        float recx = 0.0f, recy = 0.0f;
        LOADB(RA, 0);
        LOADB(RB, 8);
        LOADB(RC, 16);
        int k = 0;
        #pragma unroll 1
        for (; k + 48 <= cntp; k += 24) {
            CONSUME(RA); LOADB(RA, k + 24);
            CONSUME(RB); LOADB(RB, k + 32);
            CONSUME(RC); LOADB(RC, k + 40);
        }
        CONSUME(RA);
        CONSUME(RB);
        CONSUME(RC);

        #undef LOADB
        #undef CONSUME

        // ---- elementwise LSNN update (FMA-contracted, matches reference backend) ----
        float vd0 = __fmaf_rn(C_MEM, __fadd_rn(__fsub_rn(0.0f, v.x), cu.x), v.x);
        float vd1 = __fmaf_rn(C_MEM, __fadd_rn(__fsub_rn(0.0f, v.y), cu.y), v.y);
        float bd0 = __fmaf_rn(C_AD, __fsub_rn(1.0f, ba.x), ba.x);
        float bd1 = __fmaf_rn(C_AD, __fsub_rn(1.0f, ba.y), ba.y);
        float zz0 = (__fsub_rn(vd0, bd0) > 0.0f) ? 1.0f : 0.0f;
        float zz1 = (__fsub_rn(vd1, bd1) > 0.0f) ? 1.0f : 0.0f;
        v.x = (zz0 != 0.0f) ? 0.0f : __fadd_rn(vd0, 0.0f);
        v.y = (zz1 != 0.0f) ? 0.0f : __fadd_rn(vd1, 0.0f);
        ba.x = __fadd_rn(bd0, (zz0 != 0.0f) ? C_JP : 0.0f);
        ba.y = __fadd_rn(bd1, (zz1 != 0.0f) ? C_JP : 0.0f);
        float id0 = __fmaf_rn(-C_SYN, cu.x, cu.x);
        float id1 = __fmaf_rn(-C_SYN, cu.y, cu.y);
        cu.x = __fadd_rn(__fadd_rn(id0, xin.x), recx);
        cu.y = __fadd_rn(__fadd_rn(id1, xin.y), recy);
        z.x = zz0;
        z.y = zz1;

        __stcs((float2*)out_p, z);
        out_p += NB * NH;

        cntp = build(z);
    }

    if (write_tail) {
        size_t base = (size_t)T_STEPS * NB * NH;
        *(float2*)(out + base + 0 * (size_t)NB * NH + sb) = z;
        *(float2*)(out + base + 1 * (size_t)NB * NH + sb) = v;
        *(float2*)(out + base + 2 * (size_t)NB * NH + sb) = cu;
        *(float2*)(out + base + 3 * (size_t)NB * NH + sb) = ba;
    }
}

// ---------------------------------------------------------------------------
extern "C" void kernel_launch(void* const* d_in, const int* in_sizes, int n_in,
                              void* d_out, int out_size) {
    const float* x     = (const float*)d_in[0];
    const float* z0    = (const float*)d_in[1];
    const float* v0    = (const float*)d_in[2];
    const float* i0    = (const float*)d_in[3];
    const float* b0    = (const float*)d_in[4];
    const float* w_in  = (const float*)d_in[5];
    const float* w_rec = (const float*)d_in[6];
    float* out = (float*)d_out;

    transpose_wrec<<<dim3(16, 16), dim3(32, 8)>>>(w_rec);
    zero_pad_row<<<1, NH>>>();
    gemm_in<<<dim3((T_STEPS * NB) / 64, NH / 64), 256>>>(x, w_in);

    long long need = (long long)T_STEPS * NB * NH + 4LL * NB * NH;
    int write_tail = ((long long)out_size >= need) ? 1 : 0;
    lsnn_recurrent<<<NB, 256>>>(z0, v0, i0, b0, out, write_tail);
}